// round 1
// baseline (speedup 1.0000x reference)
#include <cuda_runtime.h>
#include <math.h>

#define NB 16
#define NS 2048
#define NIN 128
#define CHUNK 64
#define NCHUNK (NS / CHUNK)

// Scratch (device globals; no allocation allowed)
__device__ float g_h0[NB * NS];
__device__ float g_h1[NB * NS];
__device__ float g_h2[NB * NS];
__device__ float g_cs[NB * NS];   // 0.5 * |h|^2
__device__ int g_maxbits[NB];     // float bits of max d2 (>= 0)
__device__ unsigned int g_total[NB];
__device__ unsigned int g_det[NB];
__device__ unsigned int g_vert[NB];

__global__ void k_init() {
    int i = threadIdx.x;
    if (i < NB) {
        g_maxbits[i] = 0;   // 0.0f
        g_total[i] = 0u;
        g_det[i] = 0u;
        g_vert[i] = 0u;
    }
}

// h = relu(x@w1+b1)@w2+b2 ; also cs = |h|^2/2. One thread per row.
__global__ __launch_bounds__(256) void k_embed(
    const float* __restrict__ x, const float* __restrict__ w1,
    const float* __restrict__ b1, const float* __restrict__ w2,
    const float* __restrict__ b2)
{
    __shared__ float s_w1[NIN * 6];
    __shared__ float s_w2[18];
    __shared__ float s_b1[6];
    __shared__ float s_b2[3];
    for (int i = threadIdx.x; i < NIN * 6; i += blockDim.x) s_w1[i] = w1[i];
    if (threadIdx.x < 18) s_w2[threadIdx.x] = w2[threadIdx.x];
    if (threadIdx.x < 6)  s_b1[threadIdx.x] = b1[threadIdx.x];
    if (threadIdx.x < 3)  s_b2[threadIdx.x] = b2[threadIdx.x];
    __syncthreads();

    int row = blockIdx.x * blockDim.x + threadIdx.x;
    if (row >= NB * NS) return;

    const float4* xr = (const float4*)(x + (size_t)row * NIN);
    float acc[6];
#pragma unroll
    for (int e = 0; e < 6; e++) acc[e] = s_b1[e];

#pragma unroll 8
    for (int q = 0; q < NIN / 4; q++) {
        float4 v = xr[q];
#pragma unroll
        for (int e = 0; e < 6; e++) {
            acc[e] = fmaf(v.x, s_w1[(4 * q + 0) * 6 + e], acc[e]);
            acc[e] = fmaf(v.y, s_w1[(4 * q + 1) * 6 + e], acc[e]);
            acc[e] = fmaf(v.z, s_w1[(4 * q + 2) * 6 + e], acc[e]);
            acc[e] = fmaf(v.w, s_w1[(4 * q + 3) * 6 + e], acc[e]);
        }
    }
#pragma unroll
    for (int e = 0; e < 6; e++) acc[e] = fmaxf(acc[e], 0.0f);

    float h0 = s_b2[0], h1 = s_b2[1], h2 = s_b2[2];
#pragma unroll
    for (int e = 0; e < 6; e++) {
        h0 = fmaf(acc[e], s_w2[e * 3 + 0], h0);
        h1 = fmaf(acc[e], s_w2[e * 3 + 1], h1);
        h2 = fmaf(acc[e], s_w2[e * 3 + 2], h2);
    }
    g_h0[row] = h0;
    g_h1[row] = h1;
    g_h2[row] = h2;
    g_cs[row] = 0.5f * (h0 * h0 + h1 * h1 + h2 * h2);
}

// Pass 1: per-batch max of d2 = 2*max(cs_s + cs_t - dot). Uses t >= s0 symmetry.
__global__ __launch_bounds__(256) void k_max() {
    int b = blockIdx.y;
    int s0 = blockIdx.x * CHUNK;
    int tid = threadIdx.x;
    const int base = b * NS;

    __shared__ float sh0[CHUNK], sh1[CHUNK], sh2[CHUNK], shc[CHUNK];
    for (int i = tid; i < CHUNK; i += 256) {
        int r = s0 + i;
        sh0[i] = g_h0[base + r];
        sh1[i] = g_h1[base + r];
        sh2[i] = g_h2[base + r];
        shc[i] = g_cs[base + r];
    }
    __syncthreads();

    float t0[8], t1[8], t2[8], et[8];
#pragma unroll
    for (int k = 0; k < 8; k++) {
        int t = s0 + tid + k * 256;
        if (t < NS) {
            t0[k] = g_h0[base + t];
            t1[k] = g_h1[base + t];
            t2[k] = g_h2[base + t];
            et[k] = g_cs[base + t];
        } else {
            t0[k] = 0.0f; t1[k] = 0.0f; t2[k] = 0.0f;
            et[k] = -1e30f;  // never the max
        }
    }

    float m = 0.0f;  // matches fmax(d2, 0) clamp in reference
    for (int i = 0; i < CHUNK; i++) {
        float h0 = sh0[i], h1 = sh1[i], h2 = sh2[i], ce = shc[i];
#pragma unroll
        for (int k = 0; k < 8; k++) {
            float dot = fmaf(h0, t0[k], fmaf(h1, t1[k], h2 * t2[k]));
            m = fmaxf(m, (ce + et[k]) - dot);
        }
    }

    __shared__ float red[256];
    red[tid] = m;
    __syncthreads();
    for (int o = 128; o > 0; o >>= 1) {
        if (tid < o) red[tid] = fmaxf(red[tid], red[tid + o]);
        __syncthreads();
    }
    if (tid == 0) atomicMax(&g_maxbits[b], __float_as_int(2.0f * red[0]));
}

// Small kernel: super-diagonal band sum (offsets 1..9), ~18K pairs/batch.
__global__ __launch_bounds__(256) void k_det(const float* __restrict__ thp) {
    int b = blockIdx.x;
    int tid = threadIdx.x;
    const int base = b * NS;
    float th = *thp;
    float sig = 1.0f / (1.0f + expf(-th));
    float halfthr2 = 0.5f * sig * sig * __int_as_float(g_maxbits[b]);

    unsigned int sum = 0;
    for (int s = tid; s < NS; s += 256) {
        float h0 = g_h0[base + s], h1 = g_h1[base + s], h2 = g_h2[base + s];
        float cs = g_cs[base + s];
#pragma unroll
        for (int o = 1; o <= 9; o++) {
            int t = s + o;
            if (t < NS) {
                float dot = fmaf(h0, g_h0[base + t],
                            fmaf(h1, g_h1[base + t], h2 * g_h2[base + t]));
                sum += (dot > (cs + g_cs[base + t] - halfthr2)) ? 1u : 0u;
            }
        }
    }
    __shared__ unsigned int red[256];
    red[tid] = sum;
    __syncthreads();
    for (int o = 128; o > 0; o >>= 1) {
        if (tid < o) red[tid] += red[tid + o];
        __syncthreads();
    }
    if (tid == 0) g_det[b] = red[0];
}

// Pass 2: total recurrence count + vertical run-starts (length>=2).
// Block = (row chunk, batch); thread handles 8 columns, scans rows sequentially.
__global__ __launch_bounds__(256) void k_stats(const float* __restrict__ thp) {
    int b = blockIdx.y;
    int s0 = blockIdx.x * CHUNK;
    int s1 = s0 + CHUNK;
    int tid = threadIdx.x;
    const int base = b * NS;

    int rstart = (s0 == 0) ? 0 : (s0 - 1);
    int rend = (s1 < NS) ? s1 : (NS - 1);  // inclusive
    int nrows = rend - rstart + 1;

    __shared__ float sh0[CHUNK + 2], sh1[CHUNK + 2], sh2[CHUNK + 2], shc[CHUNK + 2];
    for (int i = tid; i < nrows; i += 256) {
        int r = rstart + i;
        sh0[i] = g_h0[base + r];
        sh1[i] = g_h1[base + r];
        sh2[i] = g_h2[base + r];
        shc[i] = g_cs[base + r];
    }

    float th = *thp;
    float sig = 1.0f / (1.0f + expf(-th));
    float halfthr2 = 0.5f * sig * sig * __int_as_float(g_maxbits[b]);
    __syncthreads();

    float t0[8], t1[8], t2[8], dt[8];
#pragma unroll
    for (int k = 0; k < 8; k++) {
        int t = tid + k * 256;
        t0[k] = g_h0[base + t];
        t1[k] = g_h1[base + t];
        t2[k] = g_h2[base + t];
        dt[k] = g_cs[base + t] - halfthr2;  // R <=> dot > cs + dt
    }

    int p1[8], p2[8];
    unsigned int total = 0, vert = 0;
    const int ofs = s0 - rstart;  // shared index of row s0 (0 or 1)

    // prologue: R[s0-1] (0 if s0 == 0)
    int pr[8];
    if (s0 > 0) {
        float h0 = sh0[0], h1 = sh1[0], h2 = sh2[0], cs = shc[0];
#pragma unroll
        for (int k = 0; k < 8; k++) {
            float dot = fmaf(h0, t0[k], fmaf(h1, t1[k], h2 * t2[k]));
            pr[k] = (dot > (cs + dt[k])) ? 1 : 0;
        }
    } else {
#pragma unroll
        for (int k = 0; k < 8; k++) pr[k] = 0;
    }

    // first counted row r = s0 (no vert credit for row s0-1 from this block)
    {
        float h0 = sh0[ofs], h1 = sh1[ofs], h2 = sh2[ofs], cs = shc[ofs];
#pragma unroll
        for (int k = 0; k < 8; k++) {
            float dot = fmaf(h0, t0[k], fmaf(h1, t1[k], h2 * t2[k]));
            int cur = (dot > (cs + dt[k])) ? 1 : 0;
            total += (unsigned)cur;
            p2[k] = pr[k];
            p1[k] = cur;
        }
    }

    // main loop: r = s0+1 .. s1-1 ; credits vert for row r-1
#pragma unroll 2
    for (int ii = 1; ii < CHUNK; ii++) {
        int i = ii + ofs;
        float h0 = sh0[i], h1 = sh1[i], h2 = sh2[i], cs = shc[i];
#pragma unroll
        for (int k = 0; k < 8; k++) {
            float dot = fmaf(h0, t0[k], fmaf(h1, t1[k], h2 * t2[k]));
            int cur = (dot > (cs + dt[k])) ? 1 : 0;
            total += (unsigned)cur;
            vert += (unsigned)(p1[k] & (p2[k] ^ 1) & cur);
            p2[k] = p1[k];
            p1[k] = cur;
        }
    }

    // epilogue: r = s1 -> vert credit for row s1-1 (skip if s1 == NS: next==0)
    if (s1 < NS) {
        int i = s1 - rstart;
        float h0 = sh0[i], h1 = sh1[i], h2 = sh2[i], cs = shc[i];
#pragma unroll
        for (int k = 0; k < 8; k++) {
            float dot = fmaf(h0, t0[k], fmaf(h1, t1[k], h2 * t2[k]));
            int cur = (dot > (cs + dt[k])) ? 1 : 0;
            vert += (unsigned)(p1[k] & (p2[k] ^ 1) & cur);
        }
    }

    __shared__ unsigned int rt[256], rv[256];
    rt[tid] = total;
    rv[tid] = vert;
    __syncthreads();
    for (int o = 128; o > 0; o >>= 1) {
        if (tid < o) { rt[tid] += rt[tid + o]; rv[tid] += rv[tid + o]; }
        __syncthreads();
    }
    if (tid == 0) {
        atomicAdd(&g_total[b], rt[0]);
        atomicAdd(&g_vert[b], rv[0]);
    }
}

// Final: metrics [B,4] @ w3 [4,64] + b3 -> relu
__global__ __launch_bounds__(256) void k_final(
    const float* __restrict__ w3, const float* __restrict__ b3,
    float* __restrict__ out)
{
    int tid = blockIdx.x * blockDim.x + threadIdx.x;
    if (tid >= NB * 64) return;
    int b = tid >> 6;
    int j = tid & 63;

    float total = (float)g_total[b];
    float denom = total + 1e-6f;
    float rr = total * (1.0f / ((float)NS * (float)NS));   // exact: /2^22
    float det = (float)g_det[b] / denom;
    float lam = (float)g_vert[b] / denom;
    float entr = -total * logf(1.0f + 1e-6f);

    float v = fmaf(rr, w3[j],
              fmaf(det, w3[64 + j],
              fmaf(lam, w3[128 + j],
              fmaf(entr, w3[192 + j], b3[j]))));
    out[tid] = fmaxf(v, 0.0f);
}

extern "C" void kernel_launch(void* const* d_in, const int* in_sizes, int n_in,
                              void* d_out, int out_size) {
    const float* x  = (const float*)d_in[0];
    const float* th = (const float*)d_in[1];
    const float* w1 = (const float*)d_in[2];
    const float* b1 = (const float*)d_in[3];
    const float* w2 = (const float*)d_in[4];
    const float* b2 = (const float*)d_in[5];
    const float* w3 = (const float*)d_in[6];
    const float* b3 = (const float*)d_in[7];
    float* out = (float*)d_out;

    k_init<<<1, 32>>>();
    k_embed<<<(NB * NS + 255) / 256, 256>>>(x, w1, b1, w2, b2);
    k_max<<<dim3(NCHUNK, NB), 256>>>();
    k_det<<<NB, 256>>>(th);
    k_stats<<<dim3(NCHUNK, NB), 256>>>(th);
    k_final<<<(NB * 64 + 255) / 256, 256>>>(w3, b3, out);
}

// round 2
// speedup vs baseline: 1.5508x; 1.5508x over previous
#include <cuda_runtime.h>
#include <math.h>

#define NB 16
#define NS 2048
#define NIN 128

typedef unsigned long long u64;
typedef unsigned int u32;

// ---- packed f32x2 helpers (Blackwell sm_103a) ----
__device__ __forceinline__ u64 f2fma(u64 a, u64 b, u64 c) {
    u64 d; asm("fma.rn.f32x2 %0,%1,%2,%3;" : "=l"(d) : "l"(a), "l"(b), "l"(c)); return d;
}
__device__ __forceinline__ u64 f2add(u64 a, u64 b) {
    u64 d; asm("add.rn.f32x2 %0,%1,%2;" : "=l"(d) : "l"(a), "l"(b)); return d;
}
__device__ __forceinline__ u64 pk2(float x, float y) {
    u64 d; asm("mov.b64 %0,{%1,%2};" : "=l"(d) : "f"(x), "f"(y)); return d;
}
__device__ __forceinline__ float2 unpk(u64 v) {
    float2 r; asm("mov.b64 {%0,%1},%2;" : "=f"(r.x), "=f"(r.y) : "l"(v)); return r;
}

// Scratch (device globals; no allocation allowed)
__device__ float g_h0[NB * NS];
__device__ float g_h1[NB * NS];
__device__ float g_h2[NB * NS];
__device__ float g_cs[NB * NS];        // 0.5*|h|^2 per point
__device__ ulonglong2 g_rpA[NB * NS];  // {(-h0,-h0), (-h1,-h1)} packed
__device__ ulonglong2 g_rpB[NB * NS];  // {(-h2,-h2), (cs,cs)} packed
__device__ int g_maxbits[NB];
__device__ unsigned int g_total[NB];
__device__ unsigned int g_det[NB];
__device__ unsigned int g_vert[NB];

// h = relu(x@w1+b1)@w2+b2 ; writes scalar arrays + packed-negated row arrays.
// Block 0 also resets the accumulators (runs before all consumers in stream order).
__global__ __launch_bounds__(256) void k_embed(
    const float* __restrict__ x, const float* __restrict__ w1,
    const float* __restrict__ b1, const float* __restrict__ w2,
    const float* __restrict__ b2)
{
    if (blockIdx.x == 0 && threadIdx.x < NB) {
        g_maxbits[threadIdx.x] = 0;
        g_total[threadIdx.x] = 0u;
        g_det[threadIdx.x] = 0u;
        g_vert[threadIdx.x] = 0u;
    }

    __shared__ float s_w1[NIN * 6];
    __shared__ float s_w2[18];
    __shared__ float s_b1[6];
    __shared__ float s_b2[3];
    for (int i = threadIdx.x; i < NIN * 6; i += blockDim.x) s_w1[i] = w1[i];
    if (threadIdx.x < 18) s_w2[threadIdx.x] = w2[threadIdx.x];
    if (threadIdx.x < 6)  s_b1[threadIdx.x] = b1[threadIdx.x];
    if (threadIdx.x < 3)  s_b2[threadIdx.x] = b2[threadIdx.x];
    __syncthreads();

    int row = blockIdx.x * blockDim.x + threadIdx.x;
    if (row >= NB * NS) return;

    const float4* xr = (const float4*)(x + (size_t)row * NIN);
    float acc[6];
#pragma unroll
    for (int e = 0; e < 6; e++) acc[e] = s_b1[e];

#pragma unroll 8
    for (int q = 0; q < NIN / 4; q++) {
        float4 v = xr[q];
#pragma unroll
        for (int e = 0; e < 6; e++) {
            acc[e] = fmaf(v.x, s_w1[(4 * q + 0) * 6 + e], acc[e]);
            acc[e] = fmaf(v.y, s_w1[(4 * q + 1) * 6 + e], acc[e]);
            acc[e] = fmaf(v.z, s_w1[(4 * q + 2) * 6 + e], acc[e]);
            acc[e] = fmaf(v.w, s_w1[(4 * q + 3) * 6 + e], acc[e]);
        }
    }
#pragma unroll
    for (int e = 0; e < 6; e++) acc[e] = fmaxf(acc[e], 0.0f);

    float h0 = s_b2[0], h1 = s_b2[1], h2 = s_b2[2];
#pragma unroll
    for (int e = 0; e < 6; e++) {
        h0 = fmaf(acc[e], s_w2[e * 3 + 0], h0);
        h1 = fmaf(acc[e], s_w2[e * 3 + 1], h1);
        h2 = fmaf(acc[e], s_w2[e * 3 + 2], h2);
    }
    float cs = 0.5f * (h0 * h0 + h1 * h1 + h2 * h2);
    g_h0[row] = h0;
    g_h1[row] = h1;
    g_h2[row] = h2;
    g_cs[row] = cs;
    ulonglong2 a; a.x = pk2(-h0, -h0); a.y = pk2(-h1, -h1);
    ulonglong2 b; b.x = pk2(-h2, -h2); b.y = pk2(cs, cs);
    g_rpA[row] = a;
    g_rpB[row] = b;
}

// Pass 1: per-batch max of (cs_r + cs_c - dot) over upper-triangle-covering tiles.
// grid.x = 24: x<16 -> (rc=x, cb=1); x>=16 -> (rc=x-16, cb=0, only rc<8 needed).
__global__ __launch_bounds__(256) void k_max() {
    int b = blockIdx.y;
    int xx = blockIdx.x;
    int rc, cb;
    if (xx < 16) { rc = xx; cb = 1; } else { rc = xx - 16; cb = 0; }
    int r0 = rc * 128;
    int tid = threadIdx.x;
    const int base = b * NS;

    __shared__ ulonglong2 sA[128], sB[128];
    for (int i = tid; i < 128; i += 256) {
        sA[i] = g_rpA[base + r0 + i];
        sB[i] = g_rpB[base + r0 + i];
    }
    __syncthreads();

    // two packed units per thread: cols c, c+1 and c+512, c+513
    int c0 = cb * 1024 + 2 * tid;
    int c1 = c0 + 512;
    u64 t0a = *(const u64*)(g_h0 + base + c0);
    u64 t1a = *(const u64*)(g_h1 + base + c0);
    u64 t2a = *(const u64*)(g_h2 + base + c0);
    u64 cta = *(const u64*)(g_cs + base + c0);
    u64 t0b = *(const u64*)(g_h0 + base + c1);
    u64 t1b = *(const u64*)(g_h1 + base + c1);
    u64 t2b = *(const u64*)(g_h2 + base + c1);
    u64 ctb = *(const u64*)(g_cs + base + c1);

    float m = 0.0f;
#pragma unroll 8
    for (int i = 0; i < 128; i++) {
        ulonglong2 A = sA[i];
        ulonglong2 B = sB[i];
        u64 qa = f2fma(A.x, t0a, f2fma(A.y, t1a, f2fma(B.x, t2a, f2add(B.y, cta))));
        u64 qb = f2fma(A.x, t0b, f2fma(A.y, t1b, f2fma(B.x, t2b, f2add(B.y, ctb))));
        float2 fa = unpk(qa), fb = unpk(qb);
        m = fmaxf(m, fmaxf(fmaxf(fa.x, fa.y), fmaxf(fb.x, fb.y)));
    }

    __shared__ float red[256];
    red[tid] = m;
    __syncthreads();
    for (int o = 128; o > 0; o >>= 1) {
        if (tid < o) red[tid] = fmaxf(red[tid], red[tid + o]);
        __syncthreads();
    }
    if (tid == 0) atomicMax(&g_maxbits[b], __float_as_int(2.0f * red[0]));
}

// Super-diagonal band sum (offsets 1..9). Parallelized: grid (8, NB), atomicAdd.
__global__ __launch_bounds__(256) void k_det(const float* __restrict__ thp) {
    int b = blockIdx.y;
    int tid = threadIdx.x;
    int s = blockIdx.x * 256 + tid;
    const int base = b * NS;
    float th = *thp;
    float sig = 1.0f / (1.0f + expf(-th));
    float halfthr2 = 0.5f * sig * sig * __int_as_float(g_maxbits[b]);

    unsigned int sum = 0;
    float h0 = g_h0[base + s], h1 = g_h1[base + s], h2 = g_h2[base + s];
    float cs = g_cs[base + s];
#pragma unroll
    for (int o = 1; o <= 9; o++) {
        int t = s + o;
        if (t < NS) {
            float dot = fmaf(h0, g_h0[base + t],
                        fmaf(h1, g_h1[base + t], h2 * g_h2[base + t]));
            sum += (dot > (cs + g_cs[base + t] - halfthr2)) ? 1u : 0u;
        }
    }
    __shared__ unsigned int red[256];
    red[tid] = sum;
    __syncthreads();
    for (int o = 128; o > 0; o >>= 1) {
        if (tid < o) red[tid] += red[tid + o];
        __syncthreads();
    }
    if (tid == 0) atomicAdd(&g_det[b], red[0]);
}

// Pass 2: total + vertical run-starts. Packed f32x2 compute, bit-word run detection.
// grid: x = cb + 2*rc (cb in {0,1}, rc in 0..15), y = batch. 128 rows, 1024 cols/block.
__global__ __launch_bounds__(256) void k_stats(const float* __restrict__ thp) {
    int xx = blockIdx.x;
    int cb = xx & 1;
    int rc = xx >> 1;
    int b = blockIdx.y;
    int r0 = rc * 128;
    int tid = threadIdx.x;
    const int base = b * NS;

    int rfirst = (r0 == 0) ? 0 : (r0 - 1);
    int ofs = r0 - rfirst;                       // 0 or 1
    bool has_epi = (r0 + 128 < NS);
    int nrows = 128 + ofs + (has_epi ? 1 : 0);

    __shared__ ulonglong2 sA[130], sB[130];
    for (int i = tid; i < nrows; i += 256) {
        sA[i] = g_rpA[base + rfirst + i];
        sB[i] = g_rpB[base + rfirst + i];
    }

    float th = *thp;
    float sig = 1.0f / (1.0f + expf(-th));
    float hth = 0.5f * sig * sig * __int_as_float(g_maxbits[b]);
    __syncthreads();

    int c0 = cb * 1024 + 2 * tid;
    int c1 = c0 + 512;
    u64 t0a = *(const u64*)(g_h0 + base + c0);
    u64 t1a = *(const u64*)(g_h1 + base + c0);
    u64 t2a = *(const u64*)(g_h2 + base + c0);
    float2 ca = *(const float2*)(g_cs + base + c0);
    u64 dta = pk2(ca.x - hth, ca.y - hth);
    u64 t0b = *(const u64*)(g_h0 + base + c1);
    u64 t1b = *(const u64*)(g_h1 + base + c1);
    u64 t2b = *(const u64*)(g_h2 + base + c1);
    float2 cbv = *(const float2*)(g_cs + base + c1);
    u64 dtb = pk2(cbv.x - hth, cbv.y - hth);

    // R(row i in shared) for the 4 columns, as sign bits
#define ROWBITS(i, s0o, s1o, s2o, s3o)                                          \
    {                                                                            \
        ulonglong2 A = sA[i]; ulonglong2 Bv = sB[i];                             \
        u64 qa = f2fma(A.x, t0a, f2fma(A.y, t1a, f2fma(Bv.x, t2a, f2add(Bv.y, dta)))); \
        u64 qb = f2fma(A.x, t0b, f2fma(A.y, t1b, f2fma(Bv.x, t2b, f2add(Bv.y, dtb)))); \
        float2 fa = unpk(qa), fb = unpk(qb);                                     \
        s0o = __float_as_uint(fa.x) >> 31;                                       \
        s1o = __float_as_uint(fa.y) >> 31;                                       \
        s2o = __float_as_uint(fb.x) >> 31;                                       \
        s3o = __float_as_uint(fb.y) >> 31;                                       \
    }

    u32 pcar0 = 0, pcar1 = 0, pcar2 = 0, pcar3 = 0;    // R[row-1] of oldest bit
    if (r0 > 0) ROWBITS(0, pcar0, pcar1, pcar2, pcar3);

    u32 pend0 = 0, pend1 = 0, pend2 = 0, pend3 = 0;
    u32 utot = 0, uvert = 0;

#define PROCESS(pd, pc, nf)                                                      \
    {                                                                            \
        u32 prevw = (pd >> 1) | (pc << 31);                                      \
        u32 nextw = (pd << 1) | nf;                                              \
        uvert += __popc(pd & ~prevw & nextw);                                    \
        utot += __popc(pd);                                                      \
        pc = pd & 1u;                                                            \
    }

#pragma unroll
    for (int wi = 0; wi < 4; wi++) {
        u32 w0 = 0, w1 = 0, w2 = 0, w3 = 0;
#pragma unroll 8
        for (int ii = 0; ii < 32; ii++) {
            int i = ofs + wi * 32 + ii;
            u32 s0, s1, s2, s3;
            ROWBITS(i, s0, s1, s2, s3);
            w0 = w0 + w0 + s0;
            w1 = w1 + w1 + s1;
            w2 = w2 + w2 + s2;
            w3 = w3 + w3 + s3;
        }
        if (wi > 0) {
            u32 nf0 = w0 >> 31, nf1 = w1 >> 31, nf2 = w2 >> 31, nf3 = w3 >> 31;
            PROCESS(pend0, pcar0, nf0);
            PROCESS(pend1, pcar1, nf1);
            PROCESS(pend2, pcar2, nf2);
            PROCESS(pend3, pcar3, nf3);
        }
        pend0 = w0; pend1 = w1; pend2 = w2; pend3 = w3;
    }

    u32 ne0 = 0, ne1 = 0, ne2 = 0, ne3 = 0;
    if (has_epi) ROWBITS(ofs + 128, ne0, ne1, ne2, ne3);
    PROCESS(pend0, pcar0, ne0);
    PROCESS(pend1, pcar1, ne1);
    PROCESS(pend2, pcar2, ne2);
    PROCESS(pend3, pcar3, ne3);

#undef ROWBITS
#undef PROCESS

    __shared__ unsigned int rt[256], rv[256];
    rt[tid] = utot;
    rv[tid] = uvert;
    __syncthreads();
    for (int o = 128; o > 0; o >>= 1) {
        if (tid < o) { rt[tid] += rt[tid + o]; rv[tid] += rv[tid + o]; }
        __syncthreads();
    }
    if (tid == 0) {
        atomicAdd(&g_total[b], rt[0]);
        atomicAdd(&g_vert[b], rv[0]);
    }
}

// Final: metrics [B,4] @ w3 [4,64] + b3 -> relu
__global__ __launch_bounds__(256) void k_final(
    const float* __restrict__ w3, const float* __restrict__ b3,
    float* __restrict__ out)
{
    int tid = blockIdx.x * blockDim.x + threadIdx.x;
    if (tid >= NB * 64) return;
    int b = tid >> 6;
    int j = tid & 63;

    float total = (float)g_total[b];
    float denom = total + 1e-6f;
    float rr = total * (1.0f / ((float)NS * (float)NS));
    float det = (float)g_det[b] / denom;
    float lam = (float)g_vert[b] / denom;
    float entr = -total * logf(1.0f + 1e-6f);

    float v = fmaf(rr, w3[j],
              fmaf(det, w3[64 + j],
              fmaf(lam, w3[128 + j],
              fmaf(entr, w3[192 + j], b3[j]))));
    out[tid] = fmaxf(v, 0.0f);
}

extern "C" void kernel_launch(void* const* d_in, const int* in_sizes, int n_in,
                              void* d_out, int out_size) {
    const float* x  = (const float*)d_in[0];
    const float* th = (const float*)d_in[1];
    const float* w1 = (const float*)d_in[2];
    const float* b1 = (const float*)d_in[3];
    const float* w2 = (const float*)d_in[4];
    const float* b2 = (const float*)d_in[5];
    const float* w3 = (const float*)d_in[6];
    const float* b3 = (const float*)d_in[7];
    float* out = (float*)d_out;

    k_embed<<<(NB * NS + 255) / 256, 256>>>(x, w1, b1, w2, b2);
    k_max<<<dim3(24, NB), 256>>>();
    k_det<<<dim3(8, NB), 256>>>(th);
    k_stats<<<dim3(32, NB), 256>>>(th);
    k_final<<<(NB * 64 + 255) / 256, 256>>>(w3, b3, out);
}

// round 3
// speedup vs baseline: 1.6292x; 1.0506x over previous
#include <cuda_runtime.h>
#include <math.h>

#define NB 16
#define NS 2048
#define NIN 128

typedef unsigned long long u64;
typedef unsigned int u32;

// ---- packed f32x2 helpers (Blackwell sm_103a) ----
__device__ __forceinline__ u64 f2fma(u64 a, u64 b, u64 c) {
    u64 d; asm("fma.rn.f32x2 %0,%1,%2,%3;" : "=l"(d) : "l"(a), "l"(b), "l"(c)); return d;
}
__device__ __forceinline__ u64 f2add(u64 a, u64 b) {
    u64 d; asm("add.rn.f32x2 %0,%1,%2;" : "=l"(d) : "l"(a), "l"(b)); return d;
}
__device__ __forceinline__ u64 pk2(float x, float y) {
    u64 d; asm("mov.b64 %0,{%1,%2};" : "=l"(d) : "f"(x), "f"(y)); return d;
}
__device__ __forceinline__ float2 unpk(u64 v) {
    float2 r; asm("mov.b64 {%0,%1},%2;" : "=f"(r.x), "=f"(r.y) : "l"(v)); return r;
}

// Scratch (device globals; no allocation allowed)
__device__ float g_h0[NB * NS];
__device__ float g_h1[NB * NS];
__device__ float g_h2[NB * NS];
__device__ float g_cs[NB * NS];        // 0.5*|h|^2 per point
__device__ ulonglong2 g_rpA[NB * NS];  // {(-h0,-h0), (-h1,-h1)} packed
__device__ ulonglong2 g_rpB[NB * NS];  // {(-h2,-h2), (cs,cs)} packed
__device__ int g_maxbits[NB];
__device__ unsigned int g_total[NB];
__device__ unsigned int g_det[NB];
__device__ unsigned int g_vert[NB];

// h = relu(x@w1+b1)@w2+b2 ; writes scalar arrays + packed-negated row arrays.
// 128 threads/block -> 256 blocks for occupancy on the DRAM-latency-bound x reads.
__global__ __launch_bounds__(128) void k_embed(
    const float* __restrict__ x, const float* __restrict__ w1,
    const float* __restrict__ b1, const float* __restrict__ w2,
    const float* __restrict__ b2)
{
    if (blockIdx.x == 0 && threadIdx.x < NB) {
        g_maxbits[threadIdx.x] = 0;
        g_total[threadIdx.x] = 0u;
        g_det[threadIdx.x] = 0u;
        g_vert[threadIdx.x] = 0u;
    }

    __shared__ float s_w1[NIN * 6];
    __shared__ float s_w2[18];
    __shared__ float s_b1[6];
    __shared__ float s_b2[3];
    for (int i = threadIdx.x; i < NIN * 6; i += blockDim.x) s_w1[i] = w1[i];
    if (threadIdx.x < 18) s_w2[threadIdx.x] = w2[threadIdx.x];
    if (threadIdx.x < 6)  s_b1[threadIdx.x] = b1[threadIdx.x];
    if (threadIdx.x < 3)  s_b2[threadIdx.x] = b2[threadIdx.x];
    __syncthreads();

    int row = blockIdx.x * blockDim.x + threadIdx.x;
    if (row >= NB * NS) return;

    const float4* xr = (const float4*)(x + (size_t)row * NIN);
    float acc[6];
#pragma unroll
    for (int e = 0; e < 6; e++) acc[e] = s_b1[e];

#pragma unroll 16
    for (int q = 0; q < NIN / 4; q++) {
        float4 v = xr[q];
#pragma unroll
        for (int e = 0; e < 6; e++) {
            acc[e] = fmaf(v.x, s_w1[(4 * q + 0) * 6 + e], acc[e]);
            acc[e] = fmaf(v.y, s_w1[(4 * q + 1) * 6 + e], acc[e]);
            acc[e] = fmaf(v.z, s_w1[(4 * q + 2) * 6 + e], acc[e]);
            acc[e] = fmaf(v.w, s_w1[(4 * q + 3) * 6 + e], acc[e]);
        }
    }
#pragma unroll
    for (int e = 0; e < 6; e++) acc[e] = fmaxf(acc[e], 0.0f);

    float h0 = s_b2[0], h1 = s_b2[1], h2 = s_b2[2];
#pragma unroll
    for (int e = 0; e < 6; e++) {
        h0 = fmaf(acc[e], s_w2[e * 3 + 0], h0);
        h1 = fmaf(acc[e], s_w2[e * 3 + 1], h1);
        h2 = fmaf(acc[e], s_w2[e * 3 + 2], h2);
    }
    float cs = 0.5f * (h0 * h0 + h1 * h1 + h2 * h2);
    g_h0[row] = h0;
    g_h1[row] = h1;
    g_h2[row] = h2;
    g_cs[row] = cs;
    ulonglong2 a; a.x = pk2(-h0, -h0); a.y = pk2(-h1, -h1);
    ulonglong2 b; b.x = pk2(-h2, -h2); b.y = pk2(cs, cs);
    g_rpA[row] = a;
    g_rpB[row] = b;
}

// Pass 1: per-batch max of (cs_r + cs_c - dot) over upper-triangle-covering tiles.
// 32-row x 1024-col tiles. grid.x = 96: xx<64 -> (rc=xx, cb=1); else (rc=xx-64, cb=0).
__global__ __launch_bounds__(256) void k_max() {
    int b = blockIdx.y;
    int xx = blockIdx.x;
    int rc, cb;
    if (xx < 64) { rc = xx; cb = 1; } else { rc = xx - 64; cb = 0; }
    int r0 = rc * 32;
    int tid = threadIdx.x;
    const int base = b * NS;

    __shared__ ulonglong2 sA[32], sB[32];
    if (tid < 32) {
        sA[tid] = g_rpA[base + r0 + tid];
        sB[tid] = g_rpB[base + r0 + tid];
    }
    __syncthreads();

    int c0 = cb * 1024 + 2 * tid;
    int c1 = c0 + 512;
    u64 t0a = *(const u64*)(g_h0 + base + c0);
    u64 t1a = *(const u64*)(g_h1 + base + c0);
    u64 t2a = *(const u64*)(g_h2 + base + c0);
    u64 cta = *(const u64*)(g_cs + base + c0);
    u64 t0b = *(const u64*)(g_h0 + base + c1);
    u64 t1b = *(const u64*)(g_h1 + base + c1);
    u64 t2b = *(const u64*)(g_h2 + base + c1);
    u64 ctb = *(const u64*)(g_cs + base + c1);

    float m = 0.0f;
#pragma unroll 8
    for (int i = 0; i < 32; i++) {
        ulonglong2 A = sA[i];
        ulonglong2 B = sB[i];
        u64 qa = f2fma(A.x, t0a, f2fma(A.y, t1a, f2fma(B.x, t2a, f2add(B.y, cta))));
        u64 qb = f2fma(A.x, t0b, f2fma(A.y, t1b, f2fma(B.x, t2b, f2add(B.y, ctb))));
        float2 fa = unpk(qa), fb = unpk(qb);
        m = fmaxf(m, fmaxf(fmaxf(fa.x, fa.y), fmaxf(fb.x, fb.y)));
    }

    __shared__ float red[256];
    red[tid] = m;
    __syncthreads();
    for (int o = 128; o > 0; o >>= 1) {
        if (tid < o) red[tid] = fmaxf(red[tid], red[tid + o]);
        __syncthreads();
    }
    if (tid == 0) atomicMax(&g_maxbits[b], __float_as_int(2.0f * red[0]));
}

// Super-diagonal band sum (offsets 1..9). grid (8, NB), atomicAdd.
__global__ __launch_bounds__(256) void k_det(const float* __restrict__ thp) {
    int b = blockIdx.y;
    int tid = threadIdx.x;
    int s = blockIdx.x * 256 + tid;
    const int base = b * NS;
    float th = *thp;
    float sig = 1.0f / (1.0f + expf(-th));
    float halfthr2 = 0.5f * sig * sig * __int_as_float(g_maxbits[b]);

    unsigned int sum = 0;
    float h0 = g_h0[base + s], h1 = g_h1[base + s], h2 = g_h2[base + s];
    float cs = g_cs[base + s];
#pragma unroll
    for (int o = 1; o <= 9; o++) {
        int t = s + o;
        if (t < NS) {
            float dot = fmaf(h0, g_h0[base + t],
                        fmaf(h1, g_h1[base + t], h2 * g_h2[base + t]));
            sum += (dot > (cs + g_cs[base + t] - halfthr2)) ? 1u : 0u;
        }
    }
    __shared__ unsigned int red[256];
    red[tid] = sum;
    __syncthreads();
    for (int o = 128; o > 0; o >>= 1) {
        if (tid < o) red[tid] += red[tid + o];
        __syncthreads();
    }
    if (tid == 0) atomicAdd(&g_det[b], red[0]);
}

// Pass 2: total + vertical run-starts. Packed f32x2 compute, bit-word run detection.
// 64 rows x 1024 cols per block. grid: x = cb + 2*rc (cb in {0,1}, rc 0..31), y = batch.
__global__ __launch_bounds__(256) void k_stats(const float* __restrict__ thp) {
    int xx = blockIdx.x;
    int cb = xx & 1;
    int rc = xx >> 1;
    int b = blockIdx.y;
    int r0 = rc * 64;
    int tid = threadIdx.x;
    const int base = b * NS;

    int rfirst = (r0 == 0) ? 0 : (r0 - 1);
    int ofs = r0 - rfirst;                       // 0 or 1
    bool has_epi = (r0 + 64 < NS);
    int nrows = 64 + ofs + (has_epi ? 1 : 0);

    __shared__ ulonglong2 sA[66], sB[66];
    for (int i = tid; i < nrows; i += 256) {
        sA[i] = g_rpA[base + rfirst + i];
        sB[i] = g_rpB[base + rfirst + i];
    }

    float th = *thp;
    float sig = 1.0f / (1.0f + expf(-th));
    float hth = 0.5f * sig * sig * __int_as_float(g_maxbits[b]);
    __syncthreads();

    int c0 = cb * 1024 + 2 * tid;
    int c1 = c0 + 512;
    u64 t0a = *(const u64*)(g_h0 + base + c0);
    u64 t1a = *(const u64*)(g_h1 + base + c0);
    u64 t2a = *(const u64*)(g_h2 + base + c0);
    float2 ca = *(const float2*)(g_cs + base + c0);
    u64 dta = pk2(ca.x - hth, ca.y - hth);
    u64 t0b = *(const u64*)(g_h0 + base + c1);
    u64 t1b = *(const u64*)(g_h1 + base + c1);
    u64 t2b = *(const u64*)(g_h2 + base + c1);
    float2 cbv = *(const float2*)(g_cs + base + c1);
    u64 dtb = pk2(cbv.x - hth, cbv.y - hth);

#define ROWBITS(i, s0o, s1o, s2o, s3o)                                          \
    {                                                                            \
        ulonglong2 A = sA[i]; ulonglong2 Bv = sB[i];                             \
        u64 qa = f2fma(A.x, t0a, f2fma(A.y, t1a, f2fma(Bv.x, t2a, f2add(Bv.y, dta)))); \
        u64 qb = f2fma(A.x, t0b, f2fma(A.y, t1b, f2fma(Bv.x, t2b, f2add(Bv.y, dtb)))); \
        float2 fa = unpk(qa), fb = unpk(qb);                                     \
        s0o = __float_as_uint(fa.x) >> 31;                                       \
        s1o = __float_as_uint(fa.y) >> 31;                                       \
        s2o = __float_as_uint(fb.x) >> 31;                                       \
        s3o = __float_as_uint(fb.y) >> 31;                                       \
    }

    u32 pcar0 = 0, pcar1 = 0, pcar2 = 0, pcar3 = 0;    // R[row-1] of oldest bit
    if (r0 > 0) ROWBITS(0, pcar0, pcar1, pcar2, pcar3);

    u32 pend0 = 0, pend1 = 0, pend2 = 0, pend3 = 0;
    u32 utot = 0, uvert = 0;

#define PROCESS(pd, pc, nf)                                                      \
    {                                                                            \
        u32 prevw = (pd >> 1) | (pc << 31);                                      \
        u32 nextw = (pd << 1) | nf;                                              \
        uvert += __popc(pd & ~prevw & nextw);                                    \
        utot += __popc(pd);                                                      \
        pc = pd & 1u;                                                            \
    }

#pragma unroll
    for (int wi = 0; wi < 2; wi++) {
        u32 w0 = 0, w1 = 0, w2 = 0, w3 = 0;
#pragma unroll 8
        for (int ii = 0; ii < 32; ii++) {
            int i = ofs + wi * 32 + ii;
            u32 s0, s1, s2, s3;
            ROWBITS(i, s0, s1, s2, s3);
            w0 = w0 + w0 + s0;
            w1 = w1 + w1 + s1;
            w2 = w2 + w2 + s2;
            w3 = w3 + w3 + s3;
        }
        if (wi > 0) {
            u32 nf0 = w0 >> 31, nf1 = w1 >> 31, nf2 = w2 >> 31, nf3 = w3 >> 31;
            PROCESS(pend0, pcar0, nf0);
            PROCESS(pend1, pcar1, nf1);
            PROCESS(pend2, pcar2, nf2);
            PROCESS(pend3, pcar3, nf3);
        }
        pend0 = w0; pend1 = w1; pend2 = w2; pend3 = w3;
    }

    u32 ne0 = 0, ne1 = 0, ne2 = 0, ne3 = 0;
    if (has_epi) ROWBITS(ofs + 64, ne0, ne1, ne2, ne3);
    PROCESS(pend0, pcar0, ne0);
    PROCESS(pend1, pcar1, ne1);
    PROCESS(pend2, pcar2, ne2);
    PROCESS(pend3, pcar3, ne3);

#undef ROWBITS
#undef PROCESS

    __shared__ unsigned int rt[256], rv[256];
    rt[tid] = utot;
    rv[tid] = uvert;
    __syncthreads();
    for (int o = 128; o > 0; o >>= 1) {
        if (tid < o) { rt[tid] += rt[tid + o]; rv[tid] += rv[tid + o]; }
        __syncthreads();
    }
    if (tid == 0) {
        atomicAdd(&g_total[b], rt[0]);
        atomicAdd(&g_vert[b], rv[0]);
    }
}

// Final: metrics [B,4] @ w3 [4,64] + b3 -> relu
__global__ __launch_bounds__(256) void k_final(
    const float* __restrict__ w3, const float* __restrict__ b3,
    float* __restrict__ out)
{
    int tid = blockIdx.x * blockDim.x + threadIdx.x;
    if (tid >= NB * 64) return;
    int b = tid >> 6;
    int j = tid & 63;

    float total = (float)g_total[b];
    float denom = total + 1e-6f;
    float rr = total * (1.0f / ((float)NS * (float)NS));
    float det = (float)g_det[b] / denom;
    float lam = (float)g_vert[b] / denom;
    float entr = -total * logf(1.0f + 1e-6f);

    float v = fmaf(rr, w3[j],
              fmaf(det, w3[64 + j],
              fmaf(lam, w3[128 + j],
              fmaf(entr, w3[192 + j], b3[j]))));
    out[tid] = fmaxf(v, 0.0f);
}

extern "C" void kernel_launch(void* const* d_in, const int* in_sizes, int n_in,
                              void* d_out, int out_size) {
    const float* x  = (const float*)d_in[0];
    const float* th = (const float*)d_in[1];
    const float* w1 = (const float*)d_in[2];
    const float* b1 = (const float*)d_in[3];
    const float* w2 = (const float*)d_in[4];
    const float* b2 = (const float*)d_in[5];
    const float* w3 = (const float*)d_in[6];
    const float* b3 = (const float*)d_in[7];
    float* out = (float*)d_out;

    k_embed<<<(NB * NS + 127) / 128, 128>>>(x, w1, b1, w2, b2);
    k_max<<<dim3(96, NB), 256>>>();
    k_det<<<dim3(8, NB), 256>>>(th);
    k_stats<<<dim3(64, NB), 256>>>(th);
    k_final<<<(NB * 64 + 255) / 256, 256>>>(w3, b3, out);
}